// round 4
// baseline (speedup 1.0000x reference)
#include <cuda_runtime.h>
#include <math.h>

// ---------------- problem constants ----------------
#define BB    2
#define SS    2048
#define HID   2048
#define NH    16
#define NKV   4
#define DQK   192
#define DV    128
#define LORA  512
#define QKVN  (NH*DQK + LORA)      // 3584
#define NROWS (BB*SS)              // 4096
#define KDIM  (NKV*DQK)            // 768
#define VDIM  (NKV*DV)             // 512
#define ODIM  (NH*DV)              // 2048

// ---------------- scratch (static device globals; no allocation) ----------------
__device__ float g_qkv [(size_t)NROWS * QKVN];   // [4096,3584]: q heads (0..3071) | c_kv (3072..3583)
__device__ float g_k   [(size_t)NROWS * KDIM];   // [4096,768]
__device__ float g_v   [(size_t)NROWS * VDIM];   // [4096,512]
__device__ float g_attn[(size_t)NROWS * ODIM];   // [4096,2048]

// ---------------- generic fp32 tiled GEMM: C[M,N] = A[M,K] @ B[K,N] ----------------
// 128x128 tile, BK=16, 256 threads, 8x8 per-thread. All dims multiples of tile sizes.
__global__ void __launch_bounds__(256) gemm128(
    const float* __restrict__ A, int lda,
    const float* __restrict__ B, int ldb,
    float* __restrict__ C, int ldc, int K)
{
    __shared__ float As[16][132];   // [k][m], padded
    __shared__ float Bs[16][132];   // [k][n], padded

    const int tid = threadIdx.x;
    const int m0 = blockIdx.y * 128;
    const int n0 = blockIdx.x * 128;

    const int arow = tid >> 2;            // 0..63
    const int ac4  = (tid & 3) << 2;      // 0,4,8,12
    const int brow = tid >> 6;            // 0..3
    const int bc4  = (tid & 63) << 1;     // 0..126 step 2  (we load float2? no -> use below)

    // B loader: 16x128 floats = 512 float4; thread f covers (row=f/32, col4=f%32)
    const int b_r0 = tid >> 5;            // 0..7
    const int b_c4 = (tid & 31) << 2;     // 0..124

    const int tx = tid & 15;
    const int ty = tid >> 4;

    float acc[8][8];
    #pragma unroll
    for (int i = 0; i < 8; i++)
        #pragma unroll
        for (int j = 0; j < 8; j++) acc[i][j] = 0.f;

    for (int k0 = 0; k0 < K; k0 += 16) {
        __syncthreads();
        // load A tile (128x16) transposed into As
        float4 a0 = *(const float4*)(A + (size_t)(m0 + arow)      * lda + k0 + ac4);
        float4 a1 = *(const float4*)(A + (size_t)(m0 + 64 + arow) * lda + k0 + ac4);
        As[ac4+0][arow] = a0.x; As[ac4+1][arow] = a0.y; As[ac4+2][arow] = a0.z; As[ac4+3][arow] = a0.w;
        As[ac4+0][64+arow] = a1.x; As[ac4+1][64+arow] = a1.y; As[ac4+2][64+arow] = a1.z; As[ac4+3][64+arow] = a1.w;
        // load B tile (16x128)
        float4 b0 = *(const float4*)(B + (size_t)(k0 + b_r0)     * ldb + n0 + b_c4);
        float4 b1 = *(const float4*)(B + (size_t)(k0 + 8 + b_r0) * ldb + n0 + b_c4);
        *(float4*)&Bs[b_r0][b_c4]     = b0;
        *(float4*)&Bs[b_r0 + 8][b_c4] = b1;
        __syncthreads();

        #pragma unroll
        for (int k = 0; k < 16; k++) {
            float a[8], b[8];
            *(float4*)&a[0] = *(float4*)&As[k][ty*8];
            *(float4*)&a[4] = *(float4*)&As[k][ty*8 + 4];
            *(float4*)&b[0] = *(float4*)&Bs[k][tx*8];
            *(float4*)&b[4] = *(float4*)&Bs[k][tx*8 + 4];
            #pragma unroll
            for (int i = 0; i < 8; i++)
                #pragma unroll
                for (int j = 0; j < 8; j++)
                    acc[i][j] += a[i] * b[j];
        }
    }

    #pragma unroll
    for (int i = 0; i < 8; i++) {
        float4 s0 = make_float4(acc[i][0], acc[i][1], acc[i][2], acc[i][3]);
        float4 s1 = make_float4(acc[i][4], acc[i][5], acc[i][6], acc[i][7]);
        float* cp = C + (size_t)(m0 + ty*8 + i) * ldc + n0 + tx*8;
        *(float4*)(cp)     = s0;
        *(float4*)(cp + 4) = s1;
    }
}

// ---------------- RoPE (in-place on q part of g_qkv and on g_k) ----------------
// slot < 16 : q head slot ; slot >= 16 : kv head (slot-16)
__global__ void rope_kernel(float* __restrict__ qkv, float* __restrict__ kbuf)
{
    int i = blockIdx.x * blockDim.x + threadIdx.x;
    const int total = NROWS * 20 * 32;
    if (i >= total) return;
    int p    = i & 31;
    int rest = i >> 5;
    int slot = rest % 20;
    int row  = rest / 20;
    int t    = row & (SS - 1);

    float* base = (slot < 16)
        ? (qkv  + (size_t)row * QKVN + slot * DQK + 128)
        : (kbuf + (size_t)row * KDIM + (slot - 16) * DQK + 128);

    float x1 = base[p];
    float x2 = base[p + 32];
    double f = exp(-((double)(2 * p) / 64.0) * log(10000.0));
    double ang = (double)t * f;
    double sd, cd;
    sincos(ang, &sd, &cd);
    float s = (float)sd, c = (float)cd;
    base[p]      = x1 * c - x2 * s;
    base[p + 32] = x2 * c + x1 * s;
}

// ---------------- flash attention (causal, GQA) ----------------
// grid: (32 q-tiles, 16 heads, 2 batch); 256 threads; 64x64 tiles.
#define QPAD 196
#define VPAD 132
#define SPAD 68
#define ATTN_SMEM ((64*QPAD + 64*QPAD + 64*VPAD + 64*SPAD) * 4)  // 151552 bytes

__global__ void __launch_bounds__(256) attn_kernel(
    const float* __restrict__ qkv, const float* __restrict__ kbuf,
    const float* __restrict__ vbuf, float* __restrict__ obuf)
{
    extern __shared__ float sm[];
    float* Qs = sm;                    // [64][196]
    float* Ks = Qs + 64 * QPAD;        // [64][196]
    float* Vs = Ks + 64 * QPAD;        // [64][132]
    float* Ss = Vs + 64 * VPAD;        // [64][68]

    const int qt  = gridDim.x - 1 - blockIdx.x;   // heavy tiles first
    const int h   = blockIdx.y;
    const int b   = blockIdx.z;
    const int kvh = h >> 2;
    const int tid = threadIdx.x;
    const float scale = 0.07216878364870323f;     // 1/sqrt(192)

    // load Q tile (64 x 192)
    for (int f = tid; f < 64 * 48; f += 256) {
        int r  = f / 48;
        int c4 = (f % 48) * 4;
        *(float4*)&Qs[r * QPAD + c4] =
            *(const float4*)(qkv + (size_t)(b * SS + qt * 64 + r) * QKVN + h * DQK + c4);
    }

    const int r  = tid >> 2;    // 0..63 : output row owned
    const int cg = tid & 3;     // 0..3  : col group (32 cols each)
    float m = -1e30f, l = 0.f;
    float acc[32];
    #pragma unroll
    for (int i = 0; i < 32; i++) acc[i] = 0.f;

    const int qi = tid >> 4;    // 0..15
    const int kj = tid & 15;    // 0..15

    for (int kt = 0; kt <= qt; kt++) {
        __syncthreads();
        // load K (64x192) and V (64x128)
        for (int f = tid; f < 64 * 48; f += 256) {
            int rr = f / 48, c4 = (f % 48) * 4;
            *(float4*)&Ks[rr * QPAD + c4] =
                *(const float4*)(kbuf + (size_t)(b * SS + kt * 64 + rr) * KDIM + kvh * DQK + c4);
        }
        for (int f = tid; f < 64 * 32; f += 256) {
            int rr = f / 32, c4 = (f % 32) * 4;
            *(float4*)&Vs[rr * VPAD + c4] =
                *(const float4*)(vbuf + (size_t)(b * SS + kt * 64 + rr) * VDIM + kvh * DV + c4);
        }
        __syncthreads();

        // S = Q K^T  (each thread: 4x4 sub-tile)
        {
            float c[4][4];
            #pragma unroll
            for (int a = 0; a < 4; a++)
                #pragma unroll
                for (int bb2 = 0; bb2 < 4; bb2++) c[a][bb2] = 0.f;

            #pragma unroll 4
            for (int d = 0; d < DQK; d += 4) {
                float4 qv[4], kv[4];
                #pragma unroll
                for (int a = 0; a < 4; a++)
                    qv[a] = *(float4*)&Qs[(qi * 4 + a) * QPAD + d];
                #pragma unroll
                for (int bb2 = 0; bb2 < 4; bb2++)
                    kv[bb2] = *(float4*)&Ks[(kj * 4 + bb2) * QPAD + d];
                #pragma unroll
                for (int a = 0; a < 4; a++)
                    #pragma unroll
                    for (int bb2 = 0; bb2 < 4; bb2++) {
                        c[a][bb2] += qv[a].x * kv[bb2].x;
                        c[a][bb2] += qv[a].y * kv[bb2].y;
                        c[a][bb2] += qv[a].z * kv[bb2].z;
                        c[a][bb2] += qv[a].w * kv[bb2].w;
                    }
            }
            #pragma unroll
            for (int a = 0; a < 4; a++)
                #pragma unroll
                for (int bb2 = 0; bb2 < 4; bb2++) {
                    float s = c[a][bb2] * scale;
                    if (kt == qt && (kj * 4 + bb2) > (qi * 4 + a)) s = -1e30f;
                    Ss[(qi * 4 + a) * SPAD + kj * 4 + bb2] = s;
                }
        }
        __syncthreads();

        // online softmax (4 threads per row, adjacent lanes)
        {
            float vals[16];
            float mx = -1e30f;
            #pragma unroll
            for (int j = 0; j < 16; j++) {
                vals[j] = Ss[r * SPAD + cg * 16 + j];
                mx = fmaxf(mx, vals[j]);
            }
            mx = fmaxf(mx, __shfl_xor_sync(0xffffffffu, mx, 1));
            mx = fmaxf(mx, __shfl_xor_sync(0xffffffffu, mx, 2));
            float nm = fmaxf(m, mx);
            float sum = 0.f;
            #pragma unroll
            for (int j = 0; j < 16; j++) {
                float p = __expf(vals[j] - nm);
                sum += p;
                Ss[r * SPAD + cg * 16 + j] = p;
            }
            sum += __shfl_xor_sync(0xffffffffu, sum, 1);
            sum += __shfl_xor_sync(0xffffffffu, sum, 2);
            float corr = __expf(m - nm);
            l = l * corr + sum;
            m = nm;
            #pragma unroll
            for (int i = 0; i < 32; i++) acc[i] *= corr;
        }
        __syncthreads();

        // O += P @ V  (thread owns row r, 32 cols starting cg*32)
        for (int j = 0; j < 64; j++) {
            float p = Ss[r * SPAD + j];
            #pragma unroll
            for (int i = 0; i < 8; i++) {
                float4 vv = *(float4*)&Vs[j * VPAD + cg * 32 + i * 4];
                acc[i * 4 + 0] += p * vv.x;
                acc[i * 4 + 1] += p * vv.y;
                acc[i * 4 + 2] += p * vv.z;
                acc[i * 4 + 3] += p * vv.w;
            }
        }
    }

    // epilogue
    float inv = 1.f / l;
    float* op = obuf + (size_t)(b * SS + qt * 64 + r) * ODIM + h * DV + cg * 32;
    #pragma unroll
    for (int i = 0; i < 8; i++) {
        float4 s = make_float4(acc[i*4+0]*inv, acc[i*4+1]*inv, acc[i*4+2]*inv, acc[i*4+3]*inv);
        *(float4*)(op + i * 4) = s;
    }
}

// ---------------- launch ----------------
extern "C" void kernel_launch(void* const* d_in, const int* in_sizes, int n_in,
                              void* d_out, int out_size)
{
    const float* hs   = (const float*)d_in[0];   // [2,2048,2048]
    const float* Wqkv = (const float*)d_in[1];   // [2048,3584]
    const float* Wk   = (const float*)d_in[2];   // [512,768]
    const float* Wv   = (const float*)d_in[3];   // [512,512]
    const float* Wo   = (const float*)d_in[4];   // [2048,2048]
    float* out = (float*)d_out;                  // [2,2048,2048]

    float *qkv, *kb, *vb, *ab;
    cudaGetSymbolAddress((void**)&qkv, g_qkv);
    cudaGetSymbolAddress((void**)&kb,  g_k);
    cudaGetSymbolAddress((void**)&vb,  g_v);
    cudaGetSymbolAddress((void**)&ab,  g_attn);

    // 1) qkv = hidden @ Wqkv
    gemm128<<<dim3(QKVN/128, NROWS/128), 256>>>(hs, HID, Wqkv, QKVN, qkv, QKVN, HID);
    // 2) k = c_kv @ Wk_up ; v = c_kv @ Wv_up   (c_kv is strided slice of qkv)
    gemm128<<<dim3(KDIM/128, NROWS/128), 256>>>(qkv + NH*DQK, QKVN, Wk, KDIM, kb, KDIM, LORA);
    gemm128<<<dim3(VDIM/128, NROWS/128), 256>>>(qkv + NH*DQK, QKVN, Wv, VDIM, vb, VDIM, LORA);
    // 3) RoPE in place (q heads + kv heads)
    {
        int total = NROWS * 20 * 32;
        rope_kernel<<<(total + 255) / 256, 256>>>(qkv, kb);
    }
    // 4) causal flash attention with GQA
    cudaFuncSetAttribute(attn_kernel, cudaFuncAttributeMaxDynamicSharedMemorySize, ATTN_SMEM);
    attn_kernel<<<dim3(SS/64, NH, BB), 256, ATTN_SMEM>>>(qkv, kb, vb, ab);
    // 5) out = attn @ Wo
    gemm128<<<dim3(HID/128, NROWS/128), 256>>>(ab, ODIM, Wo, HID, out, HID, HID);
}

// round 5
// speedup vs baseline: 10.2722x; 10.2722x over previous
#include <cuda_runtime.h>
#include <cuda_fp16.h>
#include <math.h>
#include <stdint.h>

// ---------------- problem constants ----------------
#define BB    2
#define SS    2048
#define HID   2048
#define NH    16
#define NKV   4
#define DQK   192
#define DV    128
#define LORA  512
#define QKVN  3584                 // NH*DQK + LORA
#define NROWS 4096                 // BB*SS
#define KDIM  768                  // NKV*DQK
#define VDIM  512                  // NKV*DV
#define ODIM  2048                 // NH*DV
#define QDIM  3072                 // NH*DQK

// ---------------- scratch (static device globals) ----------------
__device__ float  g_qkv [(size_t)NROWS * QKVN];
__device__ float  g_k   [(size_t)NROWS * KDIM];
__device__ float  g_v   [(size_t)NROWS * VDIM];
__device__ float  g_ropet[SS * 64];                 // per t: cos[32] | sin[32]
__device__ __half g_hsh  [(size_t)NROWS * HID];
__device__ __half g_wqkvT[(size_t)QKVN * HID];      // [N][K]
__device__ __half g_ckvh [(size_t)NROWS * LORA];
__device__ __half g_wkT  [(size_t)KDIM * LORA];
__device__ __half g_wvT  [(size_t)VDIM * LORA];
__device__ __half g_qh   [(size_t)NROWS * QDIM];
__device__ __half g_kh   [(size_t)NROWS * KDIM];
__device__ __half g_vh   [(size_t)NROWS * VDIM];
__device__ __half g_attnh[(size_t)NROWS * ODIM];
__device__ __half g_woT  [(size_t)HID * ODIM];      // [N=HID][K=ODIM]

// ---------------- mma / ldmatrix helpers ----------------
#define LDSM_X4(r0,r1,r2,r3,addr) \
    asm volatile("ldmatrix.sync.aligned.m8n8.x4.shared.b16 {%0,%1,%2,%3}, [%4];" \
                 : "=r"(r0), "=r"(r1), "=r"(r2), "=r"(r3) : "r"(addr))

#define LDSM_X4_T(r0,r1,r2,r3,addr) \
    asm volatile("ldmatrix.sync.aligned.m8n8.x4.trans.shared.b16 {%0,%1,%2,%3}, [%4];" \
                 : "=r"(r0), "=r"(r1), "=r"(r2), "=r"(r3) : "r"(addr))

#define MMA16816(c0,c1,c2,c3,a0,a1,a2,a3,b0,b1) \
    asm volatile("mma.sync.aligned.m16n8k16.row.col.f32.f16.f16.f32 " \
                 "{%0,%1,%2,%3}, {%4,%5,%6,%7}, {%8,%9}, {%0,%1,%2,%3};" \
                 : "+f"(c0), "+f"(c1), "+f"(c2), "+f"(c3) \
                 : "r"(a0), "r"(a1), "r"(a2), "r"(a3), "r"(b0), "r"(b1))

__device__ __forceinline__ uint32_t smaddr(const void* p) {
    return (uint32_t)__cvta_generic_to_shared(p);
}
__device__ __forceinline__ uint32_t pack2(float x, float y) {
    __half2 h = __floats2half2_rn(x, y);
    return *(uint32_t*)&h;
}

// ---------------- half GEMM: C[M,N] f32 = A[M,K] h @ Bt[N,K] h  ----------------
// 128x128x32 tile, 256 threads = 8 warps (2x4), warp tile 64x32.
__global__ void __launch_bounds__(256) hgemm(
    const __half* __restrict__ A, int lda,
    const __half* __restrict__ Bt, int ldb,
    float* __restrict__ C, int ldc, int K)
{
    __shared__ __half As[128 * 40];
    __shared__ __half Bs[128 * 40];
    const int tid = threadIdx.x, lane = tid & 31, warp = tid >> 5;
    const int wm = (warp >> 2) * 64, wn = (warp & 3) * 32;
    const int m0 = blockIdx.y * 128, n0 = blockIdx.x * 128;
    const int g = lane >> 2, q2 = (lane & 3) * 2;
    const int lr = tid >> 2, lc = (tid & 3) * 8;

    float acc[4][4][4];
    #pragma unroll
    for (int mi = 0; mi < 4; mi++)
        #pragma unroll
        for (int ni = 0; ni < 4; ni++)
            #pragma unroll
            for (int e = 0; e < 4; e++) acc[mi][ni][e] = 0.f;

    for (int k0 = 0; k0 < K; k0 += 32) {
        __syncthreads();
        *(int4*)&As[lr * 40 + lc]        = *(const int4*)&A [(size_t)(m0 + lr)      * lda + k0 + lc];
        *(int4*)&As[(lr + 64) * 40 + lc] = *(const int4*)&A [(size_t)(m0 + 64 + lr) * lda + k0 + lc];
        *(int4*)&Bs[lr * 40 + lc]        = *(const int4*)&Bt[(size_t)(n0 + lr)      * ldb + k0 + lc];
        *(int4*)&Bs[(lr + 64) * 40 + lc] = *(const int4*)&Bt[(size_t)(n0 + 64 + lr) * ldb + k0 + lc];
        __syncthreads();

        #pragma unroll
        for (int kk = 0; kk < 2; kk++) {
            const int ks = kk * 16;
            uint32_t a[4][4], bf[4][2];
            #pragma unroll
            for (int mi = 0; mi < 4; mi++) {
                uint32_t ad = smaddr(&As[(wm + mi * 16 + (lane & 15)) * 40 + ks + (lane >> 4) * 8]);
                LDSM_X4(a[mi][0], a[mi][1], a[mi][2], a[mi][3], ad);
            }
            #pragma unroll
            for (int nj = 0; nj < 2; nj++) {
                uint32_t ad = smaddr(&Bs[(wn + nj * 16 + (lane & 7) + ((lane >> 4) & 1) * 8) * 40
                                         + ks + ((lane >> 3) & 1) * 8]);
                LDSM_X4(bf[2*nj][0], bf[2*nj][1], bf[2*nj+1][0], bf[2*nj+1][1], ad);
            }
            #pragma unroll
            for (int mi = 0; mi < 4; mi++)
                #pragma unroll
                for (int ni = 0; ni < 4; ni++)
                    MMA16816(acc[mi][ni][0], acc[mi][ni][1], acc[mi][ni][2], acc[mi][ni][3],
                             a[mi][0], a[mi][1], a[mi][2], a[mi][3], bf[ni][0], bf[ni][1]);
        }
    }

    #pragma unroll
    for (int mi = 0; mi < 4; mi++)
        #pragma unroll
        for (int ni = 0; ni < 4; ni++) {
            int row = m0 + wm + mi * 16 + g;
            int col = n0 + wn + ni * 8 + q2;
            float2 v0 = make_float2(acc[mi][ni][0], acc[mi][ni][1]);
            float2 v1 = make_float2(acc[mi][ni][2], acc[mi][ni][3]);
            *(float2*)&C[(size_t)row * ldc + col]       = v0;
            *(float2*)&C[(size_t)(row + 8) * ldc + col] = v1;
        }
}

// ---------------- conversions ----------------
// strided-slice fp32 -> fp16 (dense dst)
__global__ void f2h_slice(const float* __restrict__ src, int ld, int cols, int rows,
                          __half* __restrict__ dst)
{
    int i = blockIdx.x * blockDim.x + threadIdx.x;
    int total = rows * (cols >> 2);
    if (i >= total) return;
    int row = i / (cols >> 2);
    int c4  = (i - row * (cols >> 2)) << 2;
    float4 v = *(const float4*)&src[(size_t)row * ld + c4];
    __half2 h0 = __floats2half2_rn(v.x, v.y);
    __half2 h1 = __floats2half2_rn(v.z, v.w);
    uint2 o = make_uint2(*(uint32_t*)&h0, *(uint32_t*)&h1);
    *(uint2*)&dst[(size_t)row * cols + c4] = o;
}

// W[K][N] f32 -> Wt[N][K] f16 (tiled transpose)
__global__ void transp_f2h(const float* __restrict__ W, int K, int N, __half* __restrict__ Wt)
{
    __shared__ float t[32][33];
    int n0 = blockIdx.x * 32, k0 = blockIdx.y * 32;
    int tx = threadIdx.x, ty = threadIdx.y;   // 32 x 8
    #pragma unroll
    for (int i = 0; i < 4; i++)
        t[ty + i * 8][tx] = W[(size_t)(k0 + ty + i * 8) * N + n0 + tx];
    __syncthreads();
    #pragma unroll
    for (int i = 0; i < 4; i++)
        Wt[(size_t)(n0 + ty + i * 8) * K + k0 + tx] = __float2half(t[tx][ty + i * 8]);
}

// ---------------- RoPE ----------------
__global__ void rope_table(float* __restrict__ tab)
{
    int i = blockIdx.x * blockDim.x + threadIdx.x;
    if (i >= SS * 32) return;
    int t = i >> 5, p = i & 31;
    double f = exp(-((double)(2 * p) / 64.0) * log(10000.0));
    double sd, cd;
    sincos((double)t * f, &sd, &cd);
    tab[t * 64 + p]      = (float)cd;
    tab[t * 64 + 32 + p] = (float)sd;
}

__global__ void rope_apply(float* __restrict__ qkv, float* __restrict__ kbuf,
                           const float* __restrict__ tab)
{
    int i = blockIdx.x * blockDim.x + threadIdx.x;
    const int total = NROWS * 20 * 32;
    if (i >= total) return;
    int p    = i & 31;
    int rest = i >> 5;
    int slot = rest % 20;
    int row  = rest / 20;
    int t    = row & (SS - 1);
    float* base = (slot < 16)
        ? (qkv  + (size_t)row * QKVN + slot * DQK + 128)
        : (kbuf + (size_t)row * KDIM + (slot - 16) * DQK + 128);
    float c = tab[t * 64 + p], s = tab[t * 64 + 32 + p];
    float x1 = base[p], x2 = base[p + 32];
    base[p]      = x1 * c - x2 * s;
    base[p + 32] = x2 * c + x1 * s;
}

// ---------------- flash attention (mma, causal, GQA) ----------------
// Br=128 q rows, Bc=64 kv; 8 warps, warp = 16 rows x full 64 cols.
#define QW 200   // 192 + 8 pad (halves)
#define VW 136   // 128 + 8 pad
#define ATTN_SMEM ((128*QW + 64*QW + 64*VW) * 2)   // 94208 bytes

__global__ void __launch_bounds__(256, 1) attn_kernel(
    const __half* __restrict__ qh, const __half* __restrict__ kh,
    const __half* __restrict__ vh, __half* __restrict__ oh)
{
    extern __shared__ __half sh[];
    __half* Qs = sh;                 // [128][QW]
    __half* Ks = sh + 128 * QW;      // [64][QW]
    __half* Vs = Ks + 64 * QW;       // [64][VW]

    const int qt   = gridDim.x - 1 - blockIdx.x;   // heavy tiles first
    const int h    = blockIdx.y, b = blockIdx.z, kvh = h >> 2;
    const int tid  = threadIdx.x, lane = tid & 31, warp = tid >> 5;
    const int g    = lane >> 2, q2 = (lane & 3) * 2;
    const float scale = 0.07216878364870323f;      // 1/sqrt(192)

    // load Q tile (128 x 192)
    for (int f = tid; f < 128 * 24; f += 256) {
        int r = f / 24, c = (f % 24) * 8;
        *(int4*)&Qs[r * QW + c] =
            *(const int4*)&qh[(size_t)(b * SS + qt * 128 + r) * QDIM + h * DQK + c];
    }

    float oacc[16][4];
    #pragma unroll
    for (int ni = 0; ni < 16; ni++)
        #pragma unroll
        for (int e = 0; e < 4; e++) oacc[ni][e] = 0.f;
    float m0 = -1e30f, m1 = -1e30f, l0 = 0.f, l1 = 0.f;

    const int row0 = qt * 128 + warp * 16 + g;
    const int ktend = 2 * qt + 1;

    for (int kt = 0; kt <= ktend; kt++) {
        __syncthreads();
        for (int f = tid; f < 64 * 24; f += 256) {
            int r = f / 24, c = (f % 24) * 8;
            *(int4*)&Ks[r * QW + c] =
                *(const int4*)&kh[(size_t)(b * SS + kt * 64 + r) * KDIM + kvh * DQK + c];
        }
        for (int f = tid; f < 64 * 16; f += 256) {
            int r = f / 16, c = (f % 16) * 8;
            *(int4*)&Vs[r * VW + c] =
                *(const int4*)&vh[(size_t)(b * SS + kt * 64 + r) * VDIM + kvh * DV + c];
        }
        __syncthreads();

        // ---- S = Q @ K^T  (warp: 16 x 64, K-dim 192) ----
        float sacc[8][4];
        #pragma unroll
        for (int j = 0; j < 8; j++)
            #pragma unroll
            for (int e = 0; e < 4; e++) sacc[j][e] = 0.f;

        #pragma unroll
        for (int ks = 0; ks < 12; ks++) {
            uint32_t a0, a1, a2, a3;
            uint32_t ad = smaddr(&Qs[(warp * 16 + (lane & 15)) * QW + ks * 16 + (lane >> 4) * 8]);
            LDSM_X4(a0, a1, a2, a3, ad);
            uint32_t bk[8][2];
            #pragma unroll
            for (int nj = 0; nj < 4; nj++) {
                uint32_t bd = smaddr(&Ks[(nj * 16 + (lane & 7) + ((lane >> 4) & 1) * 8) * QW
                                         + ks * 16 + ((lane >> 3) & 1) * 8]);
                LDSM_X4(bk[2*nj][0], bk[2*nj][1], bk[2*nj+1][0], bk[2*nj+1][1], bd);
            }
            #pragma unroll
            for (int nj = 0; nj < 8; nj++)
                MMA16816(sacc[nj][0], sacc[nj][1], sacc[nj][2], sacc[nj][3],
                         a0, a1, a2, a3, bk[nj][0], bk[nj][1]);
        }

        // ---- scale + causal mask + online softmax ----
        const bool diag = (kt >= 2 * qt);
        float mx0 = -1e30f, mx1 = -1e30f;
        #pragma unroll
        for (int j = 0; j < 8; j++) {
            #pragma unroll
            for (int e = 0; e < 4; e++) {
                float v = sacc[j][e] * scale;
                if (diag) {
                    int col = kt * 64 + j * 8 + q2 + (e & 1);
                    int row = row0 + ((e >= 2) ? 8 : 0);
                    if (col > row) v = -1e30f;
                }
                sacc[j][e] = v;
            }
            mx0 = fmaxf(mx0, fmaxf(sacc[j][0], sacc[j][1]));
            mx1 = fmaxf(mx1, fmaxf(sacc[j][2], sacc[j][3]));
        }
        mx0 = fmaxf(mx0, __shfl_xor_sync(0xffffffffu, mx0, 1));
        mx0 = fmaxf(mx0, __shfl_xor_sync(0xffffffffu, mx0, 2));
        mx1 = fmaxf(mx1, __shfl_xor_sync(0xffffffffu, mx1, 1));
        mx1 = fmaxf(mx1, __shfl_xor_sync(0xffffffffu, mx1, 2));
        float nm0 = fmaxf(m0, mx0), nm1 = fmaxf(m1, mx1);
        float s0 = 0.f, s1 = 0.f;
        #pragma unroll
        for (int j = 0; j < 8; j++) {
            float p0 = __expf(sacc[j][0] - nm0);
            float p1 = __expf(sacc[j][1] - nm0);
            float p2 = __expf(sacc[j][2] - nm1);
            float p3 = __expf(sacc[j][3] - nm1);
            sacc[j][0] = p0; sacc[j][1] = p1; sacc[j][2] = p2; sacc[j][3] = p3;
            s0 += p0 + p1; s1 += p2 + p3;
        }
        s0 += __shfl_xor_sync(0xffffffffu, s0, 1);
        s0 += __shfl_xor_sync(0xffffffffu, s0, 2);
        s1 += __shfl_xor_sync(0xffffffffu, s1, 1);
        s1 += __shfl_xor_sync(0xffffffffu, s1, 2);
        float c0 = __expf(m0 - nm0), c1 = __expf(m1 - nm1);
        l0 = l0 * c0 + s0; l1 = l1 * c1 + s1;
        m0 = nm0; m1 = nm1;
        #pragma unroll
        for (int ni = 0; ni < 16; ni++) {
            oacc[ni][0] *= c0; oacc[ni][1] *= c0;
            oacc[ni][2] *= c1; oacc[ni][3] *= c1;
        }

        // ---- P fragments (A operand of P@V) ----
        uint32_t pa[4][4];
        #pragma unroll
        for (int kk = 0; kk < 4; kk++) {
            pa[kk][0] = pack2(sacc[2*kk][0],   sacc[2*kk][1]);
            pa[kk][1] = pack2(sacc[2*kk][2],   sacc[2*kk][3]);
            pa[kk][2] = pack2(sacc[2*kk+1][0], sacc[2*kk+1][1]);
            pa[kk][3] = pack2(sacc[2*kk+1][2], sacc[2*kk+1][3]);
        }

        // ---- O += P @ V  (warp: 16 x 128, K-dim 64) ----
        #pragma unroll
        for (int kk = 0; kk < 4; kk++) {
            uint32_t bv[16][2];
            #pragma unroll
            for (int nj = 0; nj < 8; nj++) {
                uint32_t bd = smaddr(&Vs[(kk * 16 + (lane & 15)) * VW + nj * 16 + (lane >> 4) * 8]);
                LDSM_X4_T(bv[2*nj][0], bv[2*nj][1], bv[2*nj+1][0], bv[2*nj+1][1], bd);
            }
            #pragma unroll
            for (int ni = 0; ni < 16; ni++)
                MMA16816(oacc[ni][0], oacc[ni][1], oacc[ni][2], oacc[ni][3],
                         pa[kk][0], pa[kk][1], pa[kk][2], pa[kk][3], bv[ni][0], bv[ni][1]);
        }
    }

    // ---- epilogue: normalize + write fp16 ----
    float inv0 = 1.f / l0, inv1 = 1.f / l1;
    size_t r0 = (size_t)(b * SS) + qt * 128 + warp * 16 + g;
    #pragma unroll
    for (int ni = 0; ni < 16; ni++) {
        int col = h * DV + ni * 8 + q2;
        *(uint32_t*)&oh[r0 * ODIM + col]       = pack2(oacc[ni][0] * inv0, oacc[ni][1] * inv0);
        *(uint32_t*)&oh[(r0 + 8) * ODIM + col] = pack2(oacc[ni][2] * inv1, oacc[ni][3] * inv1);
    }
}

// ---------------- launch ----------------
extern "C" void kernel_launch(void* const* d_in, const int* in_sizes, int n_in,
                              void* d_out, int out_size)
{
    const float* hs   = (const float*)d_in[0];
    const float* Wqkv = (const float*)d_in[1];
    const float* Wk   = (const float*)d_in[2];
    const float* Wv   = (const float*)d_in[3];
    const float* Wo   = (const float*)d_in[4];
    float* out = (float*)d_out;

    float *qkv, *kb, *vb, *ropet;
    __half *hsh, *wqkvT, *ckvh, *wkT, *wvT, *qh, *kh, *vh, *attnh, *woT;
    cudaGetSymbolAddress((void**)&qkv,   g_qkv);
    cudaGetSymbolAddress((void**)&kb,    g_k);
    cudaGetSymbolAddress((void**)&vb,    g_v);
    cudaGetSymbolAddress((void**)&ropet, g_ropet);
    cudaGetSymbolAddress((void**)&hsh,   g_hsh);
    cudaGetSymbolAddress((void**)&wqkvT, g_wqkvT);
    cudaGetSymbolAddress((void**)&ckvh,  g_ckvh);
    cudaGetSymbolAddress((void**)&wkT,   g_wkT);
    cudaGetSymbolAddress((void**)&wvT,   g_wvT);
    cudaGetSymbolAddress((void**)&qh,    g_qh);
    cudaGetSymbolAddress((void**)&kh,    g_kh);
    cudaGetSymbolAddress((void**)&vh,    g_vh);
    cudaGetSymbolAddress((void**)&attnh, g_attnh);
    cudaGetSymbolAddress((void**)&woT,   g_woT);

    dim3 tb(32, 8);

    // conversions for GEMM1
    f2h_slice<<<(NROWS * (HID/4) + 255) / 256, 256>>>(hs, HID, HID, NROWS, hsh);
    transp_f2h<<<dim3(QKVN/32, HID/32), tb>>>(Wqkv, HID, QKVN, wqkvT);
    // 1) qkv
    hgemm<<<dim3(QKVN/128, NROWS/128), 256>>>(hsh, HID, wqkvT, HID, qkv, QKVN, HID);
    // conversions for GEMM2
    f2h_slice<<<(NROWS * (LORA/4) + 255) / 256, 256>>>(qkv + QDIM, QKVN, LORA, NROWS, ckvh);
    transp_f2h<<<dim3(KDIM/32, LORA/32), tb>>>(Wk, LORA, KDIM, wkT);
    transp_f2h<<<dim3(VDIM/32, LORA/32), tb>>>(Wv, LORA, VDIM, wvT);
    // 2) k, v up-proj
    hgemm<<<dim3(KDIM/128, NROWS/128), 256>>>(ckvh, LORA, wkT, LORA, kb, KDIM, LORA);
    hgemm<<<dim3(VDIM/128, NROWS/128), 256>>>(ckvh, LORA, wvT, LORA, vb, VDIM, LORA);
    // 3) RoPE (table in double, apply in float)
    rope_table<<<(SS * 32 + 255) / 256, 256>>>(ropet);
    rope_apply<<<(NROWS * 20 * 32 + 255) / 256, 256>>>(qkv, kb, ropet);
    // convert q/k/v to half
    f2h_slice<<<(NROWS * (QDIM/4) + 255) / 256, 256>>>(qkv, QKVN, QDIM, NROWS, qh);
    f2h_slice<<<(NROWS * (KDIM/4) + 255) / 256, 256>>>(kb, KDIM, KDIM, NROWS, kh);
    f2h_slice<<<(NROWS * (VDIM/4) + 255) / 256, 256>>>(vb, VDIM, VDIM, NROWS, vh);
    // 4) attention
    cudaFuncSetAttribute(attn_kernel, cudaFuncAttributeMaxDynamicSharedMemorySize, ATTN_SMEM);
    attn_kernel<<<dim3(SS/128, NH, BB), 256, ATTN_SMEM>>>(qh, kh, vh, attnh);
    // 5) output projection
    transp_f2h<<<dim3(HID/32, ODIM/32), tb>>>(Wo, ODIM, HID, woT);
    hgemm<<<dim3(HID/128, NROWS/128), 256>>>(attnh, ODIM, woT, ODIM, out, HID, ODIM);
}

// round 7
// speedup vs baseline: 13.4996x; 1.3142x over previous
#include <cuda_runtime.h>
#include <cuda_fp16.h>
#include <math.h>
#include <stdint.h>

// ---------------- problem constants ----------------
#define BB    2
#define SS    2048
#define HID   2048
#define NH    16
#define NKV   4
#define DQK   192
#define DV    128
#define LORA  512
#define QKVN  3584                 // NH*DQK + LORA
#define NROWS 4096                 // BB*SS
#define KDIM  768                  // NKV*DQK
#define VDIM  512                  // NKV*DV
#define KVD   1280                 // KDIM + VDIM (merged up-proj output)
#define ODIM  2048                 // NH*DV
#define QDIM  3072                 // NH*DQK

// ---------------- scratch (static device globals) ----------------
__device__ __align__(256) float  g_qkv [(size_t)NROWS * QKVN];
__device__ __align__(256) float  g_kv  [(size_t)NROWS * KVD];    // k (0..767) | v (768..1279)
__device__ __align__(256) float  g_ropet[SS * 64];
__device__ __align__(256) __half g_hsh  [(size_t)NROWS * HID];
__device__ __align__(256) __half g_wqkvT[(size_t)QKVN * HID];    // [N][K]
__device__ __align__(256) __half g_ckvh [(size_t)NROWS * LORA];
__device__ __align__(256) __half g_wkvT [(size_t)KVD * LORA];    // wkT rows 0..767, wvT rows 768..1279
__device__ __align__(256) __half g_qh   [(size_t)NROWS * QDIM];
__device__ __align__(256) __half g_kh   [(size_t)NROWS * KDIM];
__device__ __align__(256) __half g_vh   [(size_t)NROWS * VDIM];
__device__ __align__(256) __half g_attnh[(size_t)NROWS * ODIM];
__device__ __align__(256) __half g_woT  [(size_t)HID * ODIM];    // [N=HID][K=ODIM]

// ---------------- helpers ----------------
__device__ __forceinline__ uint32_t smaddr(const void* p) {
    return (uint32_t)__cvta_generic_to_shared(p);
}
__device__ __forceinline__ uint32_t pack2(float x, float y) {
    __half2 h = __floats2half2_rn(x, y);
    return *(uint32_t*)&h;
}
#define CP16(dst, src) \
    asm volatile("cp.async.cg.shared.global [%0], [%1], 16;" :: "r"(dst), "l"(src) : "memory")
#define CP_COMMIT() asm volatile("cp.async.commit_group;" ::: "memory")
#define CP_WAIT(n)  asm volatile("cp.async.wait_group %0;" :: "n"(n) : "memory")

#define LDSM_X4(r0,r1,r2,r3,addr) \
    asm volatile("ldmatrix.sync.aligned.m8n8.x4.shared.b16 {%0,%1,%2,%3}, [%4];" \
                 : "=r"(r0), "=r"(r1), "=r"(r2), "=r"(r3) : "r"(addr))
#define LDSM_X4_T(r0,r1,r2,r3,addr) \
    asm volatile("ldmatrix.sync.aligned.m8n8.x4.trans.shared.b16 {%0,%1,%2,%3}, [%4];" \
                 : "=r"(r0), "=r"(r1), "=r"(r2), "=r"(r3) : "r"(addr))
#define MMA16816(c0,c1,c2,c3,a0,a1,a2,a3,b0,b1) \
    asm volatile("mma.sync.aligned.m16n8k16.row.col.f32.f16.f16.f32 " \
                 "{%0,%1,%2,%3}, {%4,%5,%6,%7}, {%8,%9}, {%0,%1,%2,%3};" \
                 : "+f"(c0), "+f"(c1), "+f"(c2), "+f"(c3) \
                 : "r"(a0), "r"(a1), "r"(a2), "r"(a3), "r"(b0), "r"(b1))

// ---------------- pipelined half GEMM: C[M,N]f32 = A[M,K]h @ Bt[N,K]h ----------------
// 128x128x32 tile, 256 threads (8 warps, warp tile 64x32), 3-stage cp.async pipeline.
#define GSTG (128 * 40)                      // halves per (A or B) stage buffer
#define HGEMM_SMEM (3 * 2 * GSTG * 2)        // 61440 bytes

__global__ void __launch_bounds__(256) hgemm(
    const __half* __restrict__ A, int lda,
    const __half* __restrict__ Bt, int ldb,
    float* __restrict__ C, int ldc, int K)
{
    extern __shared__ __half hsm[];
    const int tid = threadIdx.x, lane = tid & 31, warp = tid >> 5;
    const int wm = (warp >> 2) * 64, wn = (warp & 3) * 32;
    const int m0 = blockIdx.y * 128, n0 = blockIdx.x * 128;
    const int g = lane >> 2, q2 = (lane & 3) * 2;
    const int lr = tid >> 2, lc = (tid & 3) * 8;
    const int nchunk = K >> 5;

    float acc[4][4][4];
    #pragma unroll
    for (int mi = 0; mi < 4; mi++)
        #pragma unroll
        for (int ni = 0; ni < 4; ni++)
            #pragma unroll
            for (int e = 0; e < 4; e++) acc[mi][ni][e] = 0.f;

    // prefetch stages 0,1
    #pragma unroll
    for (int p = 0; p < 2; p++) {
        __half* As = hsm + p * 2 * GSTG;
        __half* Bs = As + GSTG;
        int k0 = p * 32;
        CP16(smaddr(&As[lr * 40 + lc]),        &A [(size_t)(m0 + lr)      * lda + k0 + lc]);
        CP16(smaddr(&As[(lr + 64) * 40 + lc]), &A [(size_t)(m0 + 64 + lr) * lda + k0 + lc]);
        CP16(smaddr(&Bs[lr * 40 + lc]),        &Bt[(size_t)(n0 + lr)      * ldb + k0 + lc]);
        CP16(smaddr(&Bs[(lr + 64) * 40 + lc]), &Bt[(size_t)(n0 + 64 + lr) * ldb + k0 + lc]);
        CP_COMMIT();
    }

    for (int c = 0; c < nchunk; c++) {
        CP_WAIT(1);
        __syncthreads();
        const int s = c % 3;
        __half* As = hsm + s * 2 * GSTG;
        __half* Bs = As + GSTG;

        #pragma unroll
        for (int kk = 0; kk < 2; kk++) {
            const int ks = kk * 16;
            uint32_t a[4][4], bf[4][2];
            #pragma unroll
            for (int mi = 0; mi < 4; mi++) {
                uint32_t ad = smaddr(&As[(wm + mi * 16 + (lane & 15)) * 40 + ks + (lane >> 4) * 8]);
                LDSM_X4(a[mi][0], a[mi][1], a[mi][2], a[mi][3], ad);
            }
            #pragma unroll
            for (int nj = 0; nj < 2; nj++) {
                uint32_t ad = smaddr(&Bs[(wn + nj * 16 + (lane & 7) + ((lane >> 4) & 1) * 8) * 40
                                         + ks + ((lane >> 3) & 1) * 8]);
                LDSM_X4(bf[2*nj][0], bf[2*nj][1], bf[2*nj+1][0], bf[2*nj+1][1], ad);
            }
            #pragma unroll
            for (int mi = 0; mi < 4; mi++)
                #pragma unroll
                for (int ni = 0; ni < 4; ni++)
                    MMA16816(acc[mi][ni][0], acc[mi][ni][1], acc[mi][ni][2], acc[mi][ni][3],
                             a[mi][0], a[mi][1], a[mi][2], a[mi][3], bf[ni][0], bf[ni][1]);
        }
        __syncthreads();   // all reads of stage (c+2)%3's buffer done before refill

        if (c + 2 < nchunk) {
            const int s2 = (c + 2) % 3;
            __half* As2 = hsm + s2 * 2 * GSTG;
            __half* Bs2 = As2 + GSTG;
            int k0 = (c + 2) * 32;
            CP16(smaddr(&As2[lr * 40 + lc]),        &A [(size_t)(m0 + lr)      * lda + k0 + lc]);
            CP16(smaddr(&As2[(lr + 64) * 40 + lc]), &A [(size_t)(m0 + 64 + lr) * lda + k0 + lc]);
            CP16(smaddr(&Bs2[lr * 40 + lc]),        &Bt[(size_t)(n0 + lr)      * ldb + k0 + lc]);
            CP16(smaddr(&Bs2[(lr + 64) * 40 + lc]), &Bt[(size_t)(n0 + 64 + lr) * ldb + k0 + lc]);
        }
        CP_COMMIT();       // commit even if empty: keeps group accounting uniform
    }

    #pragma unroll
    for (int mi = 0; mi < 4; mi++)
        #pragma unroll
        for (int ni = 0; ni < 4; ni++) {
            int row = m0 + wm + mi * 16 + g;
            int col = n0 + wn + ni * 8 + q2;
            *(float2*)&C[(size_t)row * ldc + col]       = make_float2(acc[mi][ni][0], acc[mi][ni][1]);
            *(float2*)&C[(size_t)(row + 8) * ldc + col] = make_float2(acc[mi][ni][2], acc[mi][ni][3]);
        }
}

// ---------------- conversions ----------------
__global__ void f2h_slice(const float* __restrict__ src, int ld, int cols, int rows,
                          __half* __restrict__ dst)
{
    int i = blockIdx.x * blockDim.x + threadIdx.x;
    int total = rows * (cols >> 2);
    if (i >= total) return;
    int row = i / (cols >> 2);
    int c4  = (i - row * (cols >> 2)) << 2;
    float4 v = *(const float4*)&src[(size_t)row * ld + c4];
    __half2 h0 = __floats2half2_rn(v.x, v.y);
    __half2 h1 = __floats2half2_rn(v.z, v.w);
    uint2 o = make_uint2(*(uint32_t*)&h0, *(uint32_t*)&h1);
    *(uint2*)&dst[(size_t)row * cols + c4] = o;
}

__global__ void transp_f2h(const float* __restrict__ W, int K, int N, __half* __restrict__ Wt)
{
    __shared__ float t[32][33];
    int n0 = blockIdx.x * 32, k0 = blockIdx.y * 32;
    int tx = threadIdx.x, ty = threadIdx.y;   // 32 x 8
    #pragma unroll
    for (int i = 0; i < 4; i++)
        t[ty + i * 8][tx] = W[(size_t)(k0 + ty + i * 8) * N + n0 + tx];
    __syncthreads();
    #pragma unroll
    for (int i = 0; i < 4; i++)
        Wt[(size_t)(n0 + ty + i * 8) * K + k0 + tx] = __float2half(t[tx][ty + i * 8]);
}

// ---------------- RoPE ----------------
__global__ void rope_table(float* __restrict__ tab)
{
    int i = blockIdx.x * blockDim.x + threadIdx.x;
    if (i >= SS * 32) return;
    int t = i >> 5, p = i & 31;
    double f = exp(-((double)(2 * p) / 64.0) * log(10000.0));
    double sd, cd;
    sincos((double)t * f, &sd, &cd);
    tab[t * 64 + p]      = (float)cd;
    tab[t * 64 + 32 + p] = (float)sd;
}

__global__ void rope_apply(float* __restrict__ qkv, float* __restrict__ kvbuf,
                           const float* __restrict__ tab)
{
    int i = blockIdx.x * blockDim.x + threadIdx.x;
    const int total = NROWS * 20 * 32;
    if (i >= total) return;
    int p    = i & 31;
    int rest = i >> 5;
    int slot = rest % 20;
    int row  = rest / 20;
    int t    = row & (SS - 1);
    float* base = (slot < 16)
        ? (qkv   + (size_t)row * QKVN + slot * DQK + 128)
        : (kvbuf + (size_t)row * KVD + (slot - 16) * DQK + 128);
    float c = tab[t * 64 + p], s = tab[t * 64 + 32 + p];
    float x1 = base[p], x2 = base[p + 32];
    base[p]      = x1 * c - x2 * s;
    base[p + 32] = x2 * c + x1 * s;
}

// ---------------- flash attention (mma, causal, GQA, cp.async double-buffer) ----------------
#define QW 200
#define VW 136
#define ATTN_SMEM ((128*QW + 2*64*QW + 2*64*VW) * 2)   // 137216 bytes

__global__ void __launch_bounds__(256, 1) attn_kernel(
    const __half* __restrict__ qh, const __half* __restrict__ kh,
    const __half* __restrict__ vh, __half* __restrict__ oh)
{
    extern __shared__ __half sh[];
    __half* Qs  = sh;                     // [128][QW]
    __half* Ksb = sh + 128 * QW;          // 2 x [64][QW]
    __half* Vsb = Ksb + 2 * 64 * QW;      // 2 x [64][VW]

    const int qt   = gridDim.x - 1 - blockIdx.x;
    const int h    = blockIdx.y, b = blockIdx.z, kvh = h >> 2;
    const int tid  = threadIdx.x, lane = tid & 31, warp = tid >> 5;
    const int g    = lane >> 2, q2 = (lane & 3) * 2;
    const float scale = 0.07216878364870323f;

    // load Q tile (128 x 192) via cp.async
    for (int f = tid; f < 128 * 24; f += 256) {
        int r = f / 24, c = (f % 24) * 8;
        CP16(smaddr(&Qs[r * QW + c]),
             &qh[(size_t)(b * SS + qt * 128 + r) * QDIM + h * DQK + c]);
    }
    // prefetch kv tile 0 into buffer 0
    {
        const __half* kp = &kh[(size_t)(b * SS) * KDIM + kvh * DQK];
        const __half* vp = &vh[(size_t)(b * SS) * VDIM + kvh * DV];
        for (int f = tid; f < 64 * 24; f += 256) {
            int r = f / 24, c = (f % 24) * 8;
            CP16(smaddr(&Ksb[r * QW + c]), kp + (size_t)r * KDIM + c);
        }
        for (int f = tid; f < 64 * 16; f += 256) {
            int r = f / 16, c = (f % 16) * 8;
            CP16(smaddr(&Vsb[r * VW + c]), vp + (size_t)r * VDIM + c);
        }
    }
    CP_COMMIT();

    float oacc[16][4];
    #pragma unroll
    for (int ni = 0; ni < 16; ni++)
        #pragma unroll
        for (int e = 0; e < 4; e++) oacc[ni][e] = 0.f;
    float m0 = -1e30f, m1 = -1e30f, l0 = 0.f, l1 = 0.f;

    const int row0 = qt * 128 + warp * 16 + g;
    const int ktend = 2 * qt + 1;

    for (int kt = 0; kt <= ktend; kt++) {
        // prefetch next tile into other buffer
        if (kt < ktend) {
            __half* Kn = Ksb + ((kt + 1) & 1) * 64 * QW;
            __half* Vn = Vsb + ((kt + 1) & 1) * 64 * VW;
            const __half* kp = &kh[(size_t)(b * SS + (kt + 1) * 64) * KDIM + kvh * DQK];
            const __half* vp = &vh[(size_t)(b * SS + (kt + 1) * 64) * VDIM + kvh * DV];
            for (int f = tid; f < 64 * 24; f += 256) {
                int r = f / 24, c = (f % 24) * 8;
                CP16(smaddr(&Kn[r * QW + c]), kp + (size_t)r * KDIM + c);
            }
            for (int f = tid; f < 64 * 16; f += 256) {
                int r = f / 16, c = (f % 16) * 8;
                CP16(smaddr(&Vn[r * VW + c]), vp + (size_t)r * VDIM + c);
            }
        }
        CP_COMMIT();
        CP_WAIT(1);          // current tile (and Q on kt==0) resident
        __syncthreads();

        __half* Ks = Ksb + (kt & 1) * 64 * QW;
        __half* Vs = Vsb + (kt & 1) * 64 * VW;

        // ---- S = Q @ K^T ----
        float sacc[8][4];
        #pragma unroll
        for (int j = 0; j < 8; j++)
            #pragma unroll
            for (int e = 0; e < 4; e++) sacc[j][e] = 0.f;

        #pragma unroll
        for (int ks = 0; ks < 12; ks++) {
            uint32_t a0, a1, a2, a3;
            uint32_t ad = smaddr(&Qs[(warp * 16 + (lane & 15)) * QW + ks * 16 + (lane >> 4) * 8]);
            LDSM_X4(a0, a1, a2, a3, ad);
            uint32_t bk[8][2];
            #pragma unroll
            for (int nj = 0; nj < 4; nj++) {
                uint32_t bd = smaddr(&Ks[(nj * 16 + (lane & 7) + ((lane >> 4) & 1) * 8) * QW
                                         + ks * 16 + ((lane >> 3) & 1) * 8]);
                LDSM_X4(bk[2*nj][0], bk[2*nj][1], bk[2*nj+1][0], bk[2*nj+1][1], bd);
            }
            #pragma unroll
            for (int nj = 0; nj < 8; nj++)
                MMA16816(sacc[nj][0], sacc[nj][1], sacc[nj][2], sacc[nj][3],
                         a0, a1, a2, a3, bk[nj][0], bk[nj][1]);
        }

        // ---- scale + mask + online softmax ----
        const bool diag = (kt >= 2 * qt);
        float mx0 = -1e30f, mx1 = -1e30f;
        #pragma unroll
        for (int j = 0; j < 8; j++) {
            #pragma unroll
            for (int e = 0; e < 4; e++) {
                float v = sacc[j][e] * scale;
                if (diag) {
                    int col = kt * 64 + j * 8 + q2 + (e & 1);
                    int row = row0 + ((e >= 2) ? 8 : 0);
                    if (col > row) v = -1e30f;
                }
                sacc[j][e] = v;
            }
            mx0 = fmaxf(mx0, fmaxf(sacc[j][0], sacc[j][1]));
            mx1 = fmaxf(mx1, fmaxf(sacc[j][2], sacc[j][3]));
        }
        mx0 = fmaxf(mx0, __shfl_xor_sync(0xffffffffu, mx0, 1));
        mx0 = fmaxf(mx0, __shfl_xor_sync(0xffffffffu, mx0, 2));
        mx1 = fmaxf(mx1, __shfl_xor_sync(0xffffffffu, mx1, 1));
        mx1 = fmaxf(mx1, __shfl_xor_sync(0xffffffffu, mx1, 2));
        float nm0 = fmaxf(m0, mx0), nm1 = fmaxf(m1, mx1);
        float s0 = 0.f, s1 = 0.f;
        #pragma unroll
        for (int j = 0; j < 8; j++) {
            float p0 = __expf(sacc[j][0] - nm0);
            float p1 = __expf(sacc[j][1] - nm0);
            float p2 = __expf(sacc[j][2] - nm1);
            float p3 = __expf(sacc[j][3] - nm1);
            sacc[j][0] = p0; sacc[j][1] = p1; sacc[j][2] = p2; sacc[j][3] = p3;
            s0 += p0 + p1; s1 += p2 + p3;
        }
        s0 += __shfl_xor_sync(0xffffffffu, s0, 1);
        s0 += __shfl_xor_sync(0xffffffffu, s0, 2);
        s1 += __shfl_xor_sync(0xffffffffu, s1, 1);
        s1 += __shfl_xor_sync(0xffffffffu, s1, 2);
        float c0 = __expf(m0 - nm0), c1 = __expf(m1 - nm1);
        l0 = l0 * c0 + s0; l1 = l1 * c1 + s1;
        m0 = nm0; m1 = nm1;
        #pragma unroll
        for (int ni = 0; ni < 16; ni++) {
            oacc[ni][0] *= c0; oacc[ni][1] *= c0;
            oacc[ni][2] *= c1; oacc[ni][3] *= c1;
        }

        uint32_t pa[4][4];
        #pragma unroll
        for (int kk = 0; kk < 4; kk++) {
            pa[kk][0] = pack2(sacc[2*kk][0],   sacc[2*kk][1]);
            pa[kk][1] = pack2(sacc[2*kk][2],   sacc[2*kk][3]);
            pa[kk][2] = pack2(sacc[2*kk+1][0], sacc[2*kk+1][1]);
            pa[kk][3] = pack2(sacc[2*kk+1][2], sacc[2*kk+1][3]);
        }

        // ---- O += P @ V ----
        #pragma unroll
        for (int kk = 0; kk < 4; kk++) {
            uint32_t bv[16][2];
            #pragma unroll
            for (int nj = 0; nj < 8; nj++) {
                uint32_t bd = smaddr(&Vs[(kk * 16 + (lane & 15)) * VW + nj * 16 + (lane >> 4) * 8]);
                LDSM_X4_T(bv[2*nj][0], bv[2*nj][1], bv[2*nj+1][0], bv[2*nj+1][1], bd);
            }
            #pragma unroll
            for (int ni = 0; ni < 16; ni++)
                MMA16816(oacc[ni][0], oacc[ni][1], oacc[ni][2], oacc[ni][3],
                         pa[kk][0], pa[kk][1], pa[kk][2], pa[kk][3], bv[ni][0], bv[ni][1]);
        }
        __syncthreads();   // finish reading this buffer before it is refilled
    }

    float inv0 = 1.f / l0, inv1 = 1.f / l1;
    size_t r0 = (size_t)(b * SS) + qt * 128 + warp * 16 + g;
    #pragma unroll
    for (int ni = 0; ni < 16; ni++) {
        int col = h * DV + ni * 8 + q2;
        *(uint32_t*)&oh[r0 * ODIM + col]       = pack2(oacc[ni][0] * inv0, oacc[ni][1] * inv0);
        *(uint32_t*)&oh[(r0 + 8) * ODIM + col] = pack2(oacc[ni][2] * inv1, oacc[ni][3] * inv1);
    }
}

// ---------------- launch ----------------
extern "C" void kernel_launch(void* const* d_in, const int* in_sizes, int n_in,
                              void* d_out, int out_size)
{
    const float* hs   = (const float*)d_in[0];
    const float* Wqkv = (const float*)d_in[1];
    const float* Wk   = (const float*)d_in[2];
    const float* Wv   = (const float*)d_in[3];
    const float* Wo   = (const float*)d_in[4];
    float* out = (float*)d_out;

    float *qkv, *kv, *ropet;
    __half *hsh, *wqkvT, *ckvh, *wkvT, *qh, *kh, *vh, *attnh, *woT;
    cudaGetSymbolAddress((void**)&qkv,   g_qkv);
    cudaGetSymbolAddress((void**)&kv,    g_kv);
    cudaGetSymbolAddress((void**)&ropet, g_ropet);
    cudaGetSymbolAddress((void**)&hsh,   g_hsh);
    cudaGetSymbolAddress((void**)&wqkvT, g_wqkvT);
    cudaGetSymbolAddress((void**)&ckvh,  g_ckvh);
    cudaGetSymbolAddress((void**)&wkvT,  g_wkvT);
    cudaGetSymbolAddress((void**)&qh,    g_qh);
    cudaGetSymbolAddress((void**)&kh,    g_kh);
    cudaGetSymbolAddress((void**)&vh,    g_vh);
    cudaGetSymbolAddress((void**)&attnh, g_attnh);
    cudaGetSymbolAddress((void**)&woT,   g_woT);

    cudaFuncSetAttribute(hgemm, cudaFuncAttributeMaxDynamicSharedMemorySize, HGEMM_SMEM);
    cudaFuncSetAttribute(attn_kernel, cudaFuncAttributeMaxDynamicSharedMemorySize, ATTN_SMEM);

    dim3 tb(32, 8);

    // ---- GEMM1: qkv = hidden @ Wqkv ----
    f2h_slice<<<(NROWS * (HID/4) + 255) / 256, 256>>>(hs, HID, HID, NROWS, hsh);
    transp_f2h<<<dim3(QKVN/32, HID/32), tb>>>(Wqkv, HID, QKVN, wqkvT);
    hgemm<<<dim3(QKVN/128, NROWS/128), 256, HGEMM_SMEM>>>(hsh, HID, wqkvT, HID, qkv, QKVN, HID);
    // ---- GEMM2 (merged): [k|v] = c_kv @ [Wk_up|Wv_up] ----
    f2h_slice<<<(NROWS * (LORA/4) + 255) / 256, 256>>>(qkv + QDIM, QKVN, LORA, NROWS, ckvh);
    transp_f2h<<<dim3(KDIM/32, LORA/32), tb>>>(Wk, LORA, KDIM, wkvT);
    transp_f2h<<<dim3(VDIM/32, LORA/32), tb>>>(Wv, LORA, VDIM, wkvT + (size_t)KDIM * LORA);
    hgemm<<<dim3(KVD/128, NROWS/128), 256, HGEMM_SMEM>>>(ckvh, LORA, wkvT, LORA, kv, KVD, LORA);
    // ---- RoPE ----
    rope_table<<<(SS * 32 + 255) / 256, 256>>>(ropet);
    rope_apply<<<(NROWS * 20 * 32 + 255) / 256, 256>>>(qkv, kv, ropet);
    // ---- fp16 conversions for attention ----
    f2h_slice<<<(NROWS * (QDIM/4) + 255) / 256, 256>>>(qkv, QKVN, QDIM, NROWS, qh);
    f2h_slice<<<(NROWS * (KDIM/4) + 255) / 256, 256>>>(kv, KVD, KDIM, NROWS, kh);
    f2h_slice<<<(NROWS * (VDIM/4) + 255) / 256, 256>>>(kv + KDIM, KVD, VDIM, NROWS, vh);
    // ---- attention ----
    attn_kernel<<<dim3(SS/128, NH, BB), 256, ATTN_SMEM>>>(qh, kh, vh, attnh);
    // ---- GEMM3: out = attn @ Wo ----
    transp_f2h<<<dim3(HID/32, ODIM/32), tb>>>(Wo, ODIM, HID, woT);
    hgemm<<<dim3(HID/128, NROWS/128), 256, HGEMM_SMEM>>>(attnh, ODIM, woT, ODIM, out, HID, ODIM);
}

// round 10
// speedup vs baseline: 14.9120x; 1.1046x over previous
#include <cuda_runtime.h>
#include <cuda_fp16.h>
#include <math.h>
#include <stdint.h>

// ---------------- problem constants ----------------
#define BB    2
#define SS    2048
#define HID   2048
#define NH    16
#define NKV   4
#define DQK   192
#define DV    128
#define LORA  512
#define QKVN  3584                 // NH*DQK + LORA
#define NROWS 4096                 // BB*SS
#define KDIM  768                  // NKV*DQK
#define VDIM  512                  // NKV*DV
#define KVD   1280                 // KDIM + VDIM
#define ODIM  2048                 // NH*DV
#define QDIM  3072                 // NH*DQK

// ---------------- scratch (static device globals) ----------------
__device__ __align__(256) float  g_ropet[SS * 64];
__device__ __align__(256) __half g_hsh  [(size_t)NROWS * HID];
__device__ __align__(256) __half g_wqkvT[(size_t)QKVN * HID];    // [N][K]
__device__ __align__(256) __half g_wkvT [(size_t)KVD * LORA];    // [N][K], k rows then v rows
__device__ __align__(256) __half g_qkvh [(size_t)NROWS * QKVN];  // fp16 GEMM1 out: q | c_kv
__device__ __align__(256) __half g_kvh  [(size_t)NROWS * KVD];   // fp16 GEMM2 out: k | v
__device__ __align__(256) __half g_attnh[(size_t)NROWS * ODIM];
__device__ __align__(256) __half g_woT  [(size_t)HID * ODIM];    // [N=HID][K=ODIM]

// ---------------- helpers ----------------
__device__ __forceinline__ uint32_t smaddr(const void* p) {
    return (uint32_t)__cvta_generic_to_shared(p);
}
__device__ __forceinline__ uint32_t pack2(float x, float y) {
    __half2 h = __floats2half2_rn(x, y);
    return *(uint32_t*)&h;
}
__device__ __forceinline__ void store2(float* p, float a, float b) {
    *(float2*)p = make_float2(a, b);
}
__device__ __forceinline__ void store2(__half* p, float a, float b) {
    *(uint32_t*)p = pack2(a, b);
}
#define CP16(dst, src) \
    asm volatile("cp.async.cg.shared.global [%0], [%1], 16;" :: "r"(dst), "l"(src) : "memory")
#define CP_COMMIT() asm volatile("cp.async.commit_group;" ::: "memory")
#define CP_WAIT(n)  asm volatile("cp.async.wait_group %0;" :: "n"(n) : "memory")

#define LDSM_X4(r0,r1,r2,r3,addr) \
    asm volatile("ldmatrix.sync.aligned.m8n8.x4.shared.b16 {%0,%1,%2,%3}, [%4];" \
                 : "=r"(r0), "=r"(r1), "=r"(r2), "=r"(r3) : "r"(addr))
#define LDSM_X4_T(r0,r1,r2,r3,addr) \
    asm volatile("ldmatrix.sync.aligned.m8n8.x4.trans.shared.b16 {%0,%1,%2,%3}, [%4];" \
                 : "=r"(r0), "=r"(r1), "=r"(r2), "=r"(r3) : "r"(addr))
#define MMA16816(c0,c1,c2,c3,a0,a1,a2,a3,b0,b1) \
    asm volatile("mma.sync.aligned.m16n8k16.row.col.f32.f16.f16.f32 " \
                 "{%0,%1,%2,%3}, {%4,%5,%6,%7}, {%8,%9}, {%0,%1,%2,%3};" \
                 : "+f"(c0), "+f"(c1), "+f"(c2), "+f"(c3) \
                 : "r"(a0), "r"(a1), "r"(a2), "r"(a3), "r"(b0), "r"(b1))

// ---------------- pipelined half GEMM: C[M,N] = A[M,K]h @ Bt[N,K]h ----------------
// 256x128x32 CTA tile, 256 threads = 8 warps (4m x 2n), warp tile 64x64.
// 3-stage cp.async pipeline. OutT in {float, __half}.
#define ASTG (256 * 40)                          // halves per A stage
#define BSTG (128 * 40)                          // halves per B stage
#define GSTG (ASTG + BSTG)
#define HGEMM_SMEM (3 * GSTG * 2)                // 92160 bytes

template <typename OutT>
__global__ void __launch_bounds__(256, 1) hgemm256(
    const __half* __restrict__ A, int lda,
    const __half* __restrict__ Bt, int ldb,
    OutT* __restrict__ C, int ldc, int K)
{
    extern __shared__ __half hsm[];
    const int tid = threadIdx.x, lane = tid & 31, warp = tid >> 5;
    const int wm = (warp >> 1) * 64, wn = (warp & 1) * 64;
    const int m0 = blockIdx.y * 256, n0 = blockIdx.x * 128;
    const int g = lane >> 2, q2 = (lane & 3) * 2;
    const int lr = tid >> 2, lc = (tid & 3) * 8;
    const int nchunk = K >> 5;

    float acc[4][8][4];
    #pragma unroll
    for (int mi = 0; mi < 4; mi++)
        #pragma unroll
        for (int ni = 0; ni < 8; ni++)
            #pragma unroll
            for (int e = 0; e < 4; e++) acc[mi][ni][e] = 0.f;

    // prefetch stages 0,1
    #pragma unroll
    for (int p = 0; p < 2; p++) {
        __half* As = hsm + p * GSTG;
        __half* Bs = As + ASTG;
        int k0 = p * 32;
        #pragma unroll
        for (int bk = 0; bk < 4; bk++)
            CP16(smaddr(&As[(lr + 64 * bk) * 40 + lc]),
                 &A[(size_t)(m0 + 64 * bk + lr) * lda + k0 + lc]);
        #pragma unroll
        for (int bk = 0; bk < 2; bk++)
            CP16(smaddr(&Bs[(lr + 64 * bk) * 40 + lc]),
                 &Bt[(size_t)(n0 + 64 * bk + lr) * ldb + k0 + lc]);
        CP_COMMIT();
    }

    for (int c = 0; c < nchunk; c++) {
        CP_WAIT(1);
        __syncthreads();
        const int s = c % 3;
        __half* As = hsm + s * GSTG;
        __half* Bs = As + ASTG;

        #pragma unroll
        for (int kk = 0; kk < 2; kk++) {
            const int ks = kk * 16;
            uint32_t a[4][4], bf[8][2];
            #pragma unroll
            for (int mi = 0; mi < 4; mi++) {
                uint32_t ad = smaddr(&As[(wm + mi * 16 + (lane & 15)) * 40 + ks + (lane >> 4) * 8]);
                LDSM_X4(a[mi][0], a[mi][1], a[mi][2], a[mi][3], ad);
            }
            #pragma unroll
            for (int nj = 0; nj < 4; nj++) {
                uint32_t bd = smaddr(&Bs[(wn + nj * 16 + (lane & 7) + ((lane >> 4) & 1) * 8) * 40
                                         + ks + ((lane >> 3) & 1) * 8]);
                LDSM_X4(bf[2*nj][0], bf[2*nj][1], bf[2*nj+1][0], bf[2*nj+1][1], bd);
            }
            #pragma unroll
            for (int mi = 0; mi < 4; mi++)
                #pragma unroll
                for (int ni = 0; ni < 8; ni++)
                    MMA16816(acc[mi][ni][0], acc[mi][ni][1], acc[mi][ni][2], acc[mi][ni][3],
                             a[mi][0], a[mi][1], a[mi][2], a[mi][3], bf[ni][0], bf[ni][1]);
        }
        __syncthreads();

        if (c + 2 < nchunk) {
            const int s2 = (c + 2) % 3;
            __half* As2 = hsm + s2 * GSTG;
            __half* Bs2 = As2 + ASTG;
            int k0 = (c + 2) * 32;
            #pragma unroll
            for (int bk = 0; bk < 4; bk++)
                CP16(smaddr(&As2[(lr + 64 * bk) * 40 + lc]),
                     &A[(size_t)(m0 + 64 * bk + lr) * lda + k0 + lc]);
            #pragma unroll
            for (int bk = 0; bk < 2; bk++)
                CP16(smaddr(&Bs2[(lr + 64 * bk) * 40 + lc]),
                     &Bt[(size_t)(n0 + 64 * bk + lr) * ldb + k0 + lc]);
        }
        CP_COMMIT();
    }

    #pragma unroll
    for (int mi = 0; mi < 4; mi++)
        #pragma unroll
        for (int ni = 0; ni < 8; ni++) {
            int row = m0 + wm + mi * 16 + g;
            int col = n0 + wn + ni * 8 + q2;
            store2(C + (size_t)row * ldc + col,       acc[mi][ni][0], acc[mi][ni][1]);
            store2(C + (size_t)(row + 8) * ldc + col, acc[mi][ni][2], acc[mi][ni][3]);
        }
}

// ---------------- conversions ----------------
__global__ void f2h_slice(const float* __restrict__ src, int ld, int cols, int rows,
                          __half* __restrict__ dst)
{
    int i = blockIdx.x * blockDim.x + threadIdx.x;
    int total = rows * (cols >> 2);
    if (i >= total) return;
    int row = i / (cols >> 2);
    int c4  = (i - row * (cols >> 2)) << 2;
    float4 v = *(const float4*)&src[(size_t)row * ld + c4];
    __half2 h0 = __floats2half2_rn(v.x, v.y);
    __half2 h1 = __floats2half2_rn(v.z, v.w);
    uint2 o = make_uint2(*(uint32_t*)&h0, *(uint32_t*)&h1);
    *(uint2*)&dst[(size_t)row * cols + c4] = o;
}

__global__ void transp_f2h(const float* __restrict__ W, int K, int N, __half* __restrict__ Wt)
{
    __shared__ float t[32][33];
    int n0 = blockIdx.x * 32, k0 = blockIdx.y * 32;
    int tx = threadIdx.x, ty = threadIdx.y;   // 32 x 8
    #pragma unroll
    for (int i = 0; i < 4; i++)
        t[ty + i * 8][tx] = W[(size_t)(k0 + ty + i * 8) * N + n0 + tx];
    __syncthreads();
    #pragma unroll
    for (int i = 0; i < 4; i++)
        Wt[(size_t)(n0 + ty + i * 8) * K + k0 + tx] = __float2half(t[tx][ty + i * 8]);
}

// ---------------- RoPE ----------------
__global__ void rope_table(float* __restrict__ tab)
{
    int i = blockIdx.x * blockDim.x + threadIdx.x;
    if (i >= SS * 32) return;
    int t = i >> 5, p = i & 31;
    double f = exp(-((double)(2 * p) / 64.0) * log(10000.0));
    double sd, cd;
    sincos((double)t * f, &sd, &cd);
    tab[t * 64 + p]      = (float)cd;
    tab[t * 64 + 32 + p] = (float)sd;
}

// fp16 in-place rope on q slots of qkvh and k slots of kvh
__global__ void rope_apply_h(__half* __restrict__ qkvh, __half* __restrict__ kvh,
                             const float* __restrict__ tab)
{
    int i = blockIdx.x * blockDim.x + threadIdx.x;
    const int total = NROWS * 20 * 32;
    if (i >= total) return;
    int p    = i & 31;
    int rest = i >> 5;
    int slot = rest % 20;
    int row  = rest / 20;
    int t    = row & (SS - 1);
    __half* base = (slot < 16)
        ? (qkvh + (size_t)row * QKVN + slot * DQK + 128)
        : (kvh  + (size_t)row * KVD + (slot - 16) * DQK + 128);
    float c = tab[t * 64 + p], s = tab[t * 64 + 32 + p];
    float x1 = __half2float(base[p]), x2 = __half2float(base[p + 32]);
    base[p]      = __float2half(x1 * c - x2 * s);
    base[p + 32] = __float2half(x2 * c + x1 * s);
}

// ---------------- flash attention (mma, causal, GQA, cp.async double-buffer) ----------------
#define QW 200
#define VW 136
#define ATTN_SMEM ((128*QW + 2*64*QW + 2*64*VW) * 2)   // 137216 bytes

__global__ void __launch_bounds__(256, 1) attn_kernel(
    const __half* __restrict__ qp, int ldq,
    const __half* __restrict__ kp2, int ldk,
    const __half* __restrict__ vp2, int ldv,
    __half* __restrict__ oh)
{
    extern __shared__ __half sh[];
    __half* Qs  = sh;                     // [128][QW]
    __half* Ksb = sh + 128 * QW;          // 2 x [64][QW]
    __half* Vsb = Ksb + 2 * 64 * QW;      // 2 x [64][VW]

    const int qt   = gridDim.x - 1 - blockIdx.x;
    const int h    = blockIdx.y, b = blockIdx.z, hkv = h >> 2;
    const int tid  = threadIdx.x, lane = tid & 31, warp = tid >> 5;
    const int g    = lane >> 2, q2 = (lane & 3) * 2;
    const float scale = 0.07216878364870323f;

    // load Q tile (128 x 192) via cp.async
    for (int f = tid; f < 128 * 24; f += 256) {
        int r = f / 24, c = (f % 24) * 8;
        CP16(smaddr(&Qs[r * QW + c]),
             &qp[(size_t)(b * SS + qt * 128 + r) * ldq + h * DQK + c]);
    }
    // prefetch kv tile 0 into buffer 0
    {
        const __half* kp = &kp2[(size_t)(b * SS) * ldk + hkv * DQK];
        const __half* vp = &vp2[(size_t)(b * SS) * ldv + hkv * DV];
        for (int f = tid; f < 64 * 24; f += 256) {
            int r = f / 24, c = (f % 24) * 8;
            CP16(smaddr(&Ksb[r * QW + c]), kp + (size_t)r * ldk + c);
        }
        for (int f = tid; f < 64 * 16; f += 256) {
            int r = f / 16, c = (f % 16) * 8;
            CP16(smaddr(&Vsb[r * VW + c]), vp + (size_t)r * ldv + c);
        }
    }
    CP_COMMIT();

    float oacc[16][4];
    #pragma unroll
    for (int ni = 0; ni < 16; ni++)
        #pragma unroll
        for (int e = 0; e < 4; e++) oacc[ni][e] = 0.f;
    float m0 = -1e30f, m1 = -1e30f, l0 = 0.f, l1 = 0.f;

    const int row0 = qt * 128 + warp * 16 + g;
    const int ktend = 2 * qt + 1;

    for (int kt = 0; kt <= ktend; kt++) {
        if (kt < ktend) {
            __half* Kn = Ksb + ((kt + 1) & 1) * 64 * QW;
            __half* Vn = Vsb + ((kt + 1) & 1) * 64 * VW;
            const __half* kp = &kp2[(size_t)(b * SS + (kt + 1) * 64) * ldk + hkv * DQK];
            const __half* vp = &vp2[(size_t)(b * SS + (kt + 1) * 64) * ldv + hkv * DV];
            for (int f = tid; f < 64 * 24; f += 256) {
                int r = f / 24, c = (f % 24) * 8;
                CP16(smaddr(&Kn[r * QW + c]), kp + (size_t)r * ldk + c);
            }
            for (int f = tid; f < 64 * 16; f += 256) {
                int r = f / 16, c = (f % 16) * 8;
                CP16(smaddr(&Vn[r * VW + c]), vp + (size_t)r * ldv + c);
            }
        }
        CP_COMMIT();
        CP_WAIT(1);
        __syncthreads();

        __half* Ks = Ksb + (kt & 1) * 64 * QW;
        __half* Vs = Vsb + (kt & 1) * 64 * VW;

        // ---- S = Q @ K^T ----
        float sacc[8][4];
        #pragma unroll
        for (int j = 0; j < 8; j++)
            #pragma unroll
            for (int e = 0; e < 4; e++) sacc[j][e] = 0.f;

        #pragma unroll
        for (int ks = 0; ks < 12; ks++) {
            uint32_t a0, a1, a2, a3;
            uint32_t ad = smaddr(&Qs[(warp * 16 + (lane & 15)) * QW + ks * 16 + (lane >> 4) * 8]);
            LDSM_X4(a0, a1, a2, a3, ad);
            uint32_t bk[8][2];
            #pragma unroll
            for (int nj = 0; nj < 4; nj++) {
                uint32_t bd = smaddr(&Ks[(nj * 16 + (lane & 7) + ((lane >> 4) & 1) * 8) * QW
                                         + ks * 16 + ((lane >> 3) & 1) * 8]);
                LDSM_X4(bk[2*nj][0], bk[2*nj][1], bk[2*nj+1][0], bk[2*nj+1][1], bd);
            }
            #pragma unroll
            for (int nj = 0; nj < 8; nj++)
                MMA16816(sacc[nj][0], sacc[nj][1], sacc[nj][2], sacc[nj][3],
                         a0, a1, a2, a3, bk[nj][0], bk[nj][1]);
        }

        // ---- scale + mask + online softmax ----
        const bool diag = (kt >= 2 * qt);
        float mx0 = -1e30f, mx1 = -1e30f;
        #pragma unroll
        for (int j = 0; j < 8; j++) {
            #pragma unroll
            for (int e = 0; e < 4; e++) {
                float v = sacc[j][e] * scale;
                if (diag) {
                    int col = kt * 64 + j * 8 + q2 + (e & 1);
                    int row = row0 + ((e >= 2) ? 8 : 0);
                    if (col > row) v = -1e30f;
                }
                sacc[j][e] = v;
            }
            mx0 = fmaxf(mx0, fmaxf(sacc[j][0], sacc[j][1]));
            mx1 = fmaxf(mx1, fmaxf(sacc[j][2], sacc[j][3]));
        }
        mx0 = fmaxf(mx0, __shfl_xor_sync(0xffffffffu, mx0, 1));
        mx0 = fmaxf(mx0, __shfl_xor_sync(0xffffffffu, mx0, 2));
        mx1 = fmaxf(mx1, __shfl_xor_sync(0xffffffffu, mx1, 1));
        mx1 = fmaxf(mx1, __shfl_xor_sync(0xffffffffu, mx1, 2));
        float nm0 = fmaxf(m0, mx0), nm1 = fmaxf(m1, mx1);
        float s0 = 0.f, s1 = 0.f;
        #pragma unroll
        for (int j = 0; j < 8; j++) {
            float p0 = __expf(sacc[j][0] - nm0);
            float p1 = __expf(sacc[j][1] - nm0);
            float p2 = __expf(sacc[j][2] - nm1);
            float p3 = __expf(sacc[j][3] - nm1);
            sacc[j][0] = p0; sacc[j][1] = p1; sacc[j][2] = p2; sacc[j][3] = p3;
            s0 += p0 + p1; s1 += p2 + p3;
        }
        s0 += __shfl_xor_sync(0xffffffffu, s0, 1);
        s0 += __shfl_xor_sync(0xffffffffu, s0, 2);
        s1 += __shfl_xor_sync(0xffffffffu, s1, 1);
        s1 += __shfl_xor_sync(0xffffffffu, s1, 2);
        float c0 = __expf(m0 - nm0), c1 = __expf(m1 - nm1);
        l0 = l0 * c0 + s0; l1 = l1 * c1 + s1;
        m0 = nm0; m1 = nm1;
        #pragma unroll
        for (int ni = 0; ni < 16; ni++) {
            oacc[ni][0] *= c0; oacc[ni][1] *= c0;
            oacc[ni][2] *= c1; oacc[ni][3] *= c1;
        }

        uint32_t pa[4][4];
        #pragma unroll
        for (int kk = 0; kk < 4; kk++) {
            pa[kk][0] = pack2(sacc[2*kk][0],   sacc[2*kk][1]);
            pa[kk][1] = pack2(sacc[2*kk][2],   sacc[2*kk][3]);
            pa[kk][2] = pack2(sacc[2*kk+1][0], sacc[2*kk+1][1]);
            pa[kk][3] = pack2(sacc[2*kk+1][2], sacc[2*kk+1][3]);
        }

        // ---- O += P @ V ----
        #pragma unroll
        for (int kk = 0; kk < 4; kk++) {
            uint32_t bv[16][2];
            #pragma unroll
            for (int nj = 0; nj < 8; nj++) {
                uint32_t bd = smaddr(&Vs[(kk * 16 + (lane & 15)) * VW + nj * 16 + (lane >> 4) * 8]);
                LDSM_X4_T(bv[2*nj][0], bv[2*nj][1], bv[2*nj+1][0], bv[2*nj+1][1], bd);
            }
            #pragma unroll
            for (int ni = 0; ni < 16; ni++)
                MMA16816(oacc[ni][0], oacc[ni][1], oacc[ni][2], oacc[ni][3],
                         pa[kk][0], pa[kk][1], pa[kk][2], pa[kk][3], bv[ni][0], bv[ni][1]);
        }
        __syncthreads();
    }

    float inv0 = 1.f / l0, inv1 = 1.f / l1;
    size_t r0 = (size_t)(b * SS) + qt * 128 + warp * 16 + g;
    #pragma unroll
    for (int ni = 0; ni < 16; ni++) {
        int col = h * DV + ni * 8 + q2;
        *(uint32_t*)&oh[r0 * ODIM + col]       = pack2(oacc[ni][0] * inv0, oacc[ni][1] * inv0);
        *(uint32_t*)&oh[(r0 + 8) * ODIM + col] = pack2(oacc[ni][2] * inv1, oacc[ni][3] * inv1);
    }
}

// ---------------- launch ----------------
extern "C" void kernel_launch(void* const* d_in, const int* in_sizes, int n_in,
                              void* d_out, int out_size)
{
    const float* hs   = (const float*)d_in[0];
    const float* Wqkv = (const float*)d_in[1];
    const float* Wk   = (const float*)d_in[2];
    const float* Wv   = (const float*)d_in[3];
    const float* Wo   = (const float*)d_in[4];
    float* out = (float*)d_out;

    float *ropet;
    __half *hsh, *wqkvT, *wkvT, *qkvh, *kvh, *attnh, *woT;
    cudaGetSymbolAddress((void**)&ropet, g_ropet);
    cudaGetSymbolAddress((void**)&hsh,   g_hsh);
    cudaGetSymbolAddress((void**)&wqkvT, g_wqkvT);
    cudaGetSymbolAddress((void**)&wkvT,  g_wkvT);
    cudaGetSymbolAddress((void**)&qkvh,  g_qkvh);
    cudaGetSymbolAddress((void**)&kvh,   g_kvh);
    cudaGetSymbolAddress((void**)&attnh, g_attnh);
    cudaGetSymbolAddress((void**)&woT,   g_woT);

    cudaFuncSetAttribute(hgemm256<__half>, cudaFuncAttributeMaxDynamicSharedMemorySize, HGEMM_SMEM);
    cudaFuncSetAttribute(hgemm256<float>,  cudaFuncAttributeMaxDynamicSharedMemorySize, HGEMM_SMEM);
    cudaFuncSetAttribute(attn_kernel, cudaFuncAttributeMaxDynamicSharedMemorySize, ATTN_SMEM);

    dim3 tb(32, 8);

    // ---- prep: rope table + input/weight conversions ----
    rope_table<<<(SS * 32 + 255) / 256, 256>>>(ropet);
    f2h_slice<<<(NROWS * (HID/4) + 255) / 256, 256>>>(hs, HID, HID, NROWS, hsh);
    transp_f2h<<<dim3(QKVN/32, HID/32), tb>>>(Wqkv, HID, QKVN, wqkvT);
    transp_f2h<<<dim3(KDIM/32, LORA/32), tb>>>(Wk, LORA, KDIM, wkvT);
    transp_f2h<<<dim3(VDIM/32, LORA/32), tb>>>(Wv, LORA, VDIM, wkvT + (size_t)KDIM * LORA);
    transp_f2h<<<dim3(HID/32, ODIM/32), tb>>>(Wo, ODIM, HID, woT);

    // ---- GEMM1: qkvh = hidden @ Wqkv  (fp16 out) ----
    hgemm256<__half><<<dim3(QKVN/128, NROWS/256), 256, HGEMM_SMEM>>>(
        hsh, HID, wqkvT, HID, qkvh, QKVN, HID);
    // ---- GEMM2 (merged): kvh = c_kv @ [Wk|Wv]  (fp16 in-slice A, fp16 out) ----
    hgemm256<__half><<<dim3(KVD/128, NROWS/256), 256, HGEMM_SMEM>>>(
        qkvh + QDIM, QKVN, wkvT, LORA, kvh, KVD, LORA);
    // ---- RoPE in place on fp16 ----
    rope_apply_h<<<(NROWS * 20 * 32 + 255) / 256, 256>>>(qkvh, kvh, ropet);
    // ---- attention (reads strided fp16 slices directly) ----
    attn_kernel<<<dim3(SS/128, NH, BB), 256, ATTN_SMEM>>>(
        qkvh, QKVN, kvh, KVD, kvh + KDIM, KVD, attnh);
    // ---- GEMM3: out = attn @ Wo  (fp32 out) ----
    hgemm256<float><<<dim3(HID/128, NROWS/256), 256, HGEMM_SMEM>>>(
        attnh, ODIM, woT, ODIM, out, HID, ODIM);
}